// round 14
// baseline (speedup 1.0000x reference)
#include <cuda_runtime.h>
#include <cuda_bf16.h>
#include <cstdint>

// ---------------------------------------------------------------------------
// StableSpikingCoreFlow, round 14 = round 13 (110.6us) with the numerics
// margin restored: gemm0s folds Kahan every 16 k-cols (chunk SHORTER than
// round-12's proven 21.3-k chunks, which measured rel_err 0.0), and prep1g
// gains MLP-8 gathers. Everything else identical to round 13.
// ---------------------------------------------------------------------------

#define Bc 128
#define Dc 2048
#define Nc 2048
#define Tc 64
#define OUTc 1024
#define SPLITK 4
#define GT  256

#define ROWB 144             // 64 bf16 (128B) + 16B pad
#define ATILE (128 * ROWB)   // 18432 B
#define BT64  (64 * ROWB)    //  9216 B
#define BUF1  (ATILE + 3 * BT64)
#define SMEM1 (2 * BUF1)     // 92160 B
#define BUFG  (3 * ATILE + 3 * BT64)   // 82944 B
#define SMEMG (2 * BUFG)               // 165888 B

#define APIECE (Bc * Dc)

__device__ __nv_bfloat16 g_A[3 * APIECE];
__device__ float g_P[SPLITK * Bc * Nc];
__device__ float g_R0[Bc * Nc];
__device__ float g_R1[Bc * Nc];

// ---------------------------------------------------------------------------
__device__ __forceinline__ void cp16(uint32_t dst, const void* src) {
    asm volatile("cp.async.cg.shared.global [%0], [%1], 16;\n" :: "r"(dst), "l"(src));
}
#define CP_COMMIT() asm volatile("cp.async.commit_group;\n" ::: "memory")
#define CP_WAIT(n)  asm volatile("cp.async.wait_group %0;\n" :: "n"(n) : "memory")

__device__ __forceinline__ void mma16816(float* c, const uint32_t* a,
                                         uint32_t b0, uint32_t b1) {
    asm volatile(
        "mma.sync.aligned.m16n8k16.row.col.f32.bf16.bf16.f32 "
        "{%0,%1,%2,%3},{%4,%5,%6,%7},{%8,%9},{%0,%1,%2,%3};\n"
        : "+f"(c[0]), "+f"(c[1]), "+f"(c[2]), "+f"(c[3])
        : "r"(a[0]), "r"(a[1]), "r"(a[2]), "r"(a[3]), "r"(b0), "r"(b1));
}

__device__ __forceinline__ uint32_t lds32c(const char* p) {
    return *(const uint32_t*)p;
}

__device__ __forceinline__ float bfround(float v) {
    return __bfloat162float(__float2bfloat16_rn(v));
}
__device__ __forceinline__ unsigned bfu(float v) {
    return (unsigned)__bfloat16_as_ushort(__float2bfloat16_rn(v));
}
__device__ __forceinline__ uint32_t pk(unsigned lo, unsigned hi) {
    return lo | (hi << 16);
}
// v = p0+p1+p2 + O(2^-25 v); residual subtractions exact
__device__ __forceinline__ void split3(float v, unsigned& u0, unsigned& u1,
                                       unsigned& u2) {
    float r1 = v - bfround(v);
    float r2 = r1 - bfround(r1);
    u0 = bfu(v); u1 = bfu(r1); u2 = bfu(r2);
}

// exact fp32 semantics of the reference spike scan; returns COUNT (0..64)
__device__ __forceinline__ float spike_count(float a, float thr) {
    int c;
    if (a <= 0.f) c = 0;
    else if (a > thr) c = Tc;
    else {
        float m = 0.f; c = 0;
        for (int t = 0; t < Tc; t++) { m += a; if (m > thr) { m -= thr; c++; } }
    }
    return (float)c;
}

#define KFOLD(acc, ks, kc) do {                                      \
        float y = __fsub_rn((acc), (kc));                            \
        float t = __fadd_rn((ks), y);                                \
        (kc) = __fsub_rn(__fsub_rn(t, (ks)), y);                     \
        (ks) = t;                                                    \
        (acc) = 0.f;                                                 \
    } while (0)

// ---------------------------------------------------------------------------
// layer-0 prep: gather + split 64*x into 3 bf16 piece matrices (2 k/thread)
__global__ void prep0a_kernel(const float* __restrict__ x,
                              const int* __restrict__ axon) {
    int idx = blockIdx.x * blockDim.x + threadIdx.x;
    if (idx >= Bc * Dc / 2) return;
    int b = idx >> 10, a = (idx & 1023) * 2;
    unsigned p0, p1, p2, q0, q1, q2;
    split3(64.0f * x[(b << 11) + axon[a]],     p0, p1, p2);
    split3(64.0f * x[(b << 11) + axon[a + 1]], q0, q1, q2);
    size_t off = (size_t)b * Dc + a;
    *(uint32_t*)(g_A + off)              = pk(p0, q0);
    *(uint32_t*)(g_A + APIECE + off)     = pk(p1, q1);
    *(uint32_t*)(g_A + 2 * APIECE + off) = pk(p2, q2);
}

// layers>=1 prep: gather counts (exact bf16), 8 gathers per thread (MLP 8)
__global__ void prep1g_kernel(const float* __restrict__ R,
                              const int* __restrict__ axon) {
    int t = blockIdx.x * blockDim.x + threadIdx.x;
    if (t >= Bc * Dc / 8) return;
    int b = t >> 8;                 // 256 threads per batch row
    int a = (t & 255) * 8;
    int ix[8];
#pragma unroll
    for (int i = 0; i < 8; i++) ix[i] = axon[a + i];
    float v[8];
#pragma unroll
    for (int i = 0; i < 8; i++) v[i] = R[(b << 11) + ix[i]];
    uint32_t* dst = (uint32_t*)(g_A + (size_t)b * Dc + a);
#pragma unroll
    for (int i = 0; i < 4; i++)
        dst[i] = pk(bfu(v[2 * i]), bfu(v[2 * i + 1]));
}

// ---------------------------------------------------------------------------
// layer-0 GEMM: 6 piece-pairs, W split in-kernel, splitK=4,
// Kahan fold every kk (16 k-cols -> chunk shorter than proven 21.3-k).
__global__ __launch_bounds__(GT, 1)
void gemm0s_kernel(const float* __restrict__ W) {
    extern __shared__ char smch[];
    const int tid = threadIdx.x;
    const int w = tid >> 5, lane = tid & 31;
    const int wm = w & 3, wn = w >> 2;
    const int g = lane >> 2, tig = lane & 3;
    const int bn = blockIdx.x * 64;
    const size_t k0 = (size_t)blockIdx.y * (Dc / SPLITK);
    const uint32_t smb = (uint32_t)__cvta_generic_to_shared(smch);
    const int nPh = (Dc / SPLITK) / 64;   // 8

    const int ch = tid & 7;
    const int arow = tid >> 3;
    const uint32_t dAbase = smb + arow * ROWB + ch * 16;
    const size_t sAoff = (size_t)arow * Dc + k0 + ch * 8;

    const int vrow = tid >> 2;
    const int vq   = tid & 3;
    const float* wp = W + (size_t)(bn + vrow) * Dc + k0 + vq * 4;
    const uint32_t bsts = smb + 3 * ATILE + vrow * ROWB + vq * 8;

#define FA0(p, buf) do {                                                     \
        uint32_t bo = (uint32_t)(buf) * BUFG;                                \
        _Pragma("unroll")                                                    \
        for (int pc = 0; pc < 3; pc++)                                       \
            _Pragma("unroll")                                                \
            for (int r = 0; r < 4; r++)                                      \
                cp16(dAbase + bo + pc * ATILE + r * (32 * ROWB),             \
                     g_A + pc * APIECE + sAoff + (size_t)r * (32 * Dc)       \
                         + (size_t)(p) * 64);                                \
        CP_COMMIT();                                                         \
    } while (0)

#define WLOAD(wr, p) do {                                                    \
        _Pragma("unroll")                                                    \
        for (int jj = 0; jj < 4; jj++)                                       \
            wr[jj] = *(const float4*)(wp + (size_t)(p) * 64 + jj * 16);      \
    } while (0)

#define FB0(buf, wr) do {                                                    \
        uint32_t ba = bsts + (uint32_t)(buf) * BUFG;                         \
        _Pragma("unroll")                                                    \
        for (int jj = 0; jj < 4; jj++) {                                     \
            float e4[4] = {wr[jj].x, wr[jj].y, wr[jj].z, wr[jj].w};          \
            unsigned q0[4], q1[4], q2[4];                                    \
            _Pragma("unroll")                                                \
            for (int i = 0; i < 4; i++)                                      \
                split3(e4[i], q0[i], q1[i], q2[i]);                          \
            uint32_t col = ba + jj * 32;                                     \
            asm volatile("st.shared.v2.b32 [%0], {%1,%2};\n"                 \
                :: "r"(col), "r"(pk(q0[0], q0[1])), "r"(pk(q0[2], q0[3]))); \
            asm volatile("st.shared.v2.b32 [%0], {%1,%2};\n"                 \
                :: "r"(col + BT64), "r"(pk(q1[0], q1[1])), "r"(pk(q1[2], q1[3]))); \
            asm volatile("st.shared.v2.b32 [%0], {%1,%2};\n"                 \
                :: "r"(col + 2 * BT64), "r"(pk(q2[0], q2[1])), "r"(pk(q2[2], q2[3]))); \
        }                                                                    \
    } while (0)

    float acc[2][4][4], ks[2][4][4], kc[2][4][4];
#pragma unroll
    for (int mt = 0; mt < 2; mt++)
#pragma unroll
        for (int j = 0; j < 4; j++)
#pragma unroll
            for (int q = 0; q < 4; q++) {
                acc[mt][j][q] = 0.f; ks[mt][j][q] = 0.f; kc[mt][j][q] = 0.f;
            }

    float4 wr[4];
    WLOAD(wr, 0); FB0(0, wr); FA0(0, 0);
    WLOAD(wr, 1); FB0(1, wr); FA0(1, 1);
    WLOAD(wr, 2);

    for (int p = 0; p < nPh; p++) {
        if (p + 1 < nPh) { CP_WAIT(1); } else { CP_WAIT(0); }
        __syncthreads();
        const char* Ab = smch + (p & 1) * BUFG;
        const char* Bb = Ab + 3 * ATILE;
#pragma unroll
        for (int kk = 0; kk < 4; kk++) {
            uint32_t a[3][2][4];
#pragma unroll
            for (int pc = 0; pc < 3; pc++)
#pragma unroll
                for (int mt = 0; mt < 2; mt++) {
                    const char* ap = Ab + pc * ATILE
                                   + (wm * 32 + mt * 16 + g) * ROWB
                                   + kk * 32 + tig * 4;
                    a[pc][mt][0] = lds32c(ap);
                    a[pc][mt][1] = lds32c(ap + 8 * ROWB);
                    a[pc][mt][2] = lds32c(ap + 16);
                    a[pc][mt][3] = lds32c(ap + 8 * ROWB + 16);
                }
#pragma unroll
            for (int j = 0; j < 4; j++) {
                const char* brow = Bb + (wn * 32 + j * 8 + g) * ROWB
                                 + kk * 32 + tig * 4;
                uint32_t b00 = lds32c(brow);
                uint32_t b01 = lds32c(brow + 16);
                uint32_t b10 = lds32c(brow + BT64);
                uint32_t b11 = lds32c(brow + BT64 + 16);
                uint32_t b20 = lds32c(brow + 2 * BT64);
                uint32_t b21 = lds32c(brow + 2 * BT64 + 16);
#pragma unroll
                for (int mt = 0; mt < 2; mt++) {
                    mma16816(acc[mt][j], a[0][mt], b00, b01);  // a0*w0
                    mma16816(acc[mt][j], a[0][mt], b10, b11);  // a0*w1
                    mma16816(acc[mt][j], a[0][mt], b20, b21);  // a0*w2
                    mma16816(acc[mt][j], a[1][mt], b00, b01);  // a1*w0
                    mma16816(acc[mt][j], a[1][mt], b10, b11);  // a1*w1
                    mma16816(acc[mt][j], a[2][mt], b00, b01);  // a2*w0
                }
            }
            // Kahan fold every kk: chunk = 16 full-magnitude k + corrections
#pragma unroll
            for (int mt = 0; mt < 2; mt++)
#pragma unroll
                for (int j = 0; j < 4; j++)
#pragma unroll
                    for (int q = 0; q < 4; q++)
                        KFOLD(acc[mt][j][q], ks[mt][j][q], kc[mt][j][q]);
        }
        __syncthreads();
        if (p + 2 < nPh) {
            FB0(p & 1, wr);
            FA0(p + 2, p & 1);
            if (p + 3 < nPh) WLOAD(wr, p + 3);
        }
    }
#undef FA0
#undef FB0
#undef WLOAD

    float* plane = g_P + (size_t)blockIdx.y * (Bc * Nc);
#pragma unroll
    for (int mt = 0; mt < 2; mt++)
#pragma unroll
        for (int j = 0; j < 4; j++) {
            int m = wm * 32 + mt * 16 + g;
            int n = bn + wn * 32 + j * 8 + 2 * tig;
            float r0 = __fsub_rn(ks[mt][j][0], kc[mt][j][0]);
            float r1 = __fsub_rn(ks[mt][j][1], kc[mt][j][1]);
            float r2 = __fsub_rn(ks[mt][j][2], kc[mt][j][2]);
            float r3 = __fsub_rn(ks[mt][j][3], kc[mt][j][3]);
            *(float2*)&plane[(size_t)m * Nc + n]       = make_float2(r0, r1);
            *(float2*)&plane[(size_t)(m + 8) * Nc + n] = make_float2(r2, r3);
        }
}

// ---------------------------------------------------------------------------
// layers>=1 GEMM: identical to rounds 12/13 (measured rel_err 0.0)
__global__ __launch_bounds__(GT, 1)
void gemm1s_kernel(const float* __restrict__ W) {
    extern __shared__ char smch[];
    const int tid = threadIdx.x;
    const int w = tid >> 5, lane = tid & 31;
    const int wm = w & 3, wn = w >> 2;
    const int g = lane >> 2, tig = lane & 3;
    const int bn = blockIdx.x * 64;
    const size_t k0 = (size_t)blockIdx.y * (Dc / SPLITK);
    const uint32_t smb = (uint32_t)__cvta_generic_to_shared(smch);
    const int nPh = (Dc / SPLITK) / 64;   // 8

    const int ch = tid & 7;
    const __nv_bfloat16* sA[4];
    uint32_t dA[4];
#pragma unroll
    for (int r = 0; r < 4; r++) {
        int row = (tid + r * GT) >> 3;
        sA[r] = g_A + (size_t)row * Dc + k0 + ch * 8;
        dA[r] = smb + row * ROWB + ch * 16;
    }

    const int vrow = tid >> 2;
    const int vq   = tid & 3;
    const float* wp = W + (size_t)(bn + vrow) * Dc + k0 + vq * 4;
    const uint32_t bsts = smb + ATILE + vrow * ROWB + vq * 8;

#define FA(p, buf) do {                                             \
        uint32_t bo = (uint32_t)(buf) * BUF1;                       \
        _Pragma("unroll")                                           \
        for (int r = 0; r < 4; r++)                                 \
            cp16(dA[r] + bo, sA[r] + (size_t)(p) * 64);             \
        CP_COMMIT();                                                \
    } while (0)

#define WLOAD(wr, p) do {                                           \
        _Pragma("unroll")                                           \
        for (int jj = 0; jj < 4; jj++)                              \
            wr[jj] = *(const float4*)(wp + (size_t)(p) * 64 + jj * 16); \
    } while (0)

#define FB(buf, wr) do {                                            \
        uint32_t ba = bsts + (uint32_t)(buf) * BUF1;                \
        _Pragma("unroll")                                           \
        for (int jj = 0; jj < 4; jj++) {                            \
            float e4[4] = {wr[jj].x, wr[jj].y, wr[jj].z, wr[jj].w}; \
            unsigned q0[4], q1[4], q2[4];                           \
            _Pragma("unroll")                                       \
            for (int i = 0; i < 4; i++)                             \
                split3(e4[i], q0[i], q1[i], q2[i]);                 \
            uint32_t col = ba + jj * 32;                            \
            asm volatile("st.shared.v2.b32 [%0], {%1,%2};\n"        \
                :: "r"(col), "r"(pk(q0[0], q0[1])), "r"(pk(q0[2], q0[3]))); \
            asm volatile("st.shared.v2.b32 [%0], {%1,%2};\n"        \
                :: "r"(col + 64 * ROWB), "r"(pk(q1[0], q1[1])), "r"(pk(q1[2], q1[3]))); \
            asm volatile("st.shared.v2.b32 [%0], {%1,%2};\n"        \
                :: "r"(col + 128 * ROWB), "r"(pk(q2[0], q2[1])), "r"(pk(q2[2], q2[3]))); \
        }                                                           \
    } while (0)

    float acc[2][4][4], ks[2][4][4], kc[2][4][4];
#pragma unroll
    for (int mt = 0; mt < 2; mt++)
#pragma unroll
        for (int j = 0; j < 4; j++)
#pragma unroll
            for (int q = 0; q < 4; q++) {
                acc[mt][j][q] = 0.f; ks[mt][j][q] = 0.f; kc[mt][j][q] = 0.f;
            }

    float4 wr[4];
    WLOAD(wr, 0); FB(0, wr); FA(0, 0);
    WLOAD(wr, 1); FB(1, wr); FA(1, 1);
    WLOAD(wr, 2);

    for (int p = 0; p < nPh; p++) {
        if (p + 1 < nPh) { CP_WAIT(1); } else { CP_WAIT(0); }
        __syncthreads();
        const char* Ab = smch + (p & 1) * BUF1;
        const char* Bb = Ab + ATILE;
#pragma unroll
        for (int kk = 0; kk < 4; kk++) {
            uint32_t a[2][4];
#pragma unroll
            for (int mt = 0; mt < 2; mt++) {
                const char* ap = Ab + (wm * 32 + mt * 16 + g) * ROWB
                               + kk * 32 + tig * 4;
                a[mt][0] = lds32c(ap);
                a[mt][1] = lds32c(ap + 8 * ROWB);
                a[mt][2] = lds32c(ap + 16);
                a[mt][3] = lds32c(ap + 8 * ROWB + 16);
            }
#pragma unroll
            for (int pc = 0; pc < 3; pc++) {
#pragma unroll
                for (int j = 0; j < 4; j++) {
                    const char* bp = Bb + pc * (64 * ROWB)
                                   + (wn * 32 + j * 8 + g) * ROWB
                                   + kk * 32 + tig * 4;
                    uint32_t b0 = lds32c(bp);
                    uint32_t b1 = lds32c(bp + 16);
                    mma16816(acc[0][j], a[0], b0, b1);
                    mma16816(acc[1][j], a[1], b0, b1);
                }
            }
        }
        __syncthreads();
        if (p + 2 < nPh) {
            FB(p & 1, wr);
            FA(p + 2, p & 1);
            if (p + 3 < nPh) WLOAD(wr, p + 3);
        }

#pragma unroll
        for (int mt = 0; mt < 2; mt++)
#pragma unroll
            for (int j = 0; j < 4; j++)
#pragma unroll
                for (int q = 0; q < 4; q++)
                    KFOLD(acc[mt][j][q], ks[mt][j][q], kc[mt][j][q]);
    }
#undef FA
#undef FB
#undef WLOAD

    float* plane = g_P + (size_t)blockIdx.y * (Bc * Nc);
#pragma unroll
    for (int mt = 0; mt < 2; mt++)
#pragma unroll
        for (int j = 0; j < 4; j++) {
            int m = wm * 32 + mt * 16 + g;
            int n = bn + wn * 32 + j * 8 + 2 * tig;
            float r0 = __fsub_rn(ks[mt][j][0], kc[mt][j][0]);
            float r1 = __fsub_rn(ks[mt][j][1], kc[mt][j][1]);
            float r2 = __fsub_rn(ks[mt][j][2], kc[mt][j][2]);
            float r3 = __fsub_rn(ks[mt][j][3], kc[mt][j][3]);
            *(float2*)&plane[(size_t)m * Nc + n]       = make_float2(r0, r1);
            *(float2*)&plane[(size_t)(m + 8) * Nc + n] = make_float2(r2, r3);
        }
}

// ---------------------------------------------------------------------------
__global__ void scan_kernel(const float* __restrict__ thr, int l,
                            float* __restrict__ R) {
    int idx = blockIdx.x * blockDim.x + threadIdx.x;
    if (idx >= Bc * Nc) return;
    float e0 = g_P[0 * (Bc * Nc) + idx];
    float e1 = g_P[1 * (Bc * Nc) + idx];
    float e2 = g_P[2 * (Bc * Nc) + idx];
    float e3 = g_P[3 * (Bc * Nc) + idx];
    float s = __fadd_rn(__fadd_rn(e0, e1), __fadd_rn(e2, e3));
    R[idx] = spike_count(s * 0.015625f, thr[l]);   // /64 exact
}

__global__ void out_kernel(const float* __restrict__ R,
                           const int* __restrict__ out_idx,
                           float* __restrict__ out) {
    int idx = blockIdx.x * blockDim.x + threadIdx.x;
    if (idx >= Bc * OUTc) return;
    int b = idx >> 10, o = idx & 1023;
    out[idx] = R[(b << 11) + out_idx[o]];          // already counts
}

// ---------------------------------------------------------------------------
extern "C" void kernel_launch(void* const* d_in, const int* in_sizes, int n_in,
                              void* d_out, int out_size)
{
    const float* x       = (const float*)d_in[0];
    const float* W       = (const float*)d_in[1];
    const float* thr     = (const float*)d_in[2];
    const int*   axon    = (const int*)  d_in[3];
    const int*   out_idx = (const int*)  d_in[4];
    (void)in_sizes; (void)n_in; (void)out_size;

    cudaFuncSetAttribute(gemm0s_kernel,
                         cudaFuncAttributeMaxDynamicSharedMemorySize, SMEMG);
    cudaFuncSetAttribute(gemm1s_kernel,
                         cudaFuncAttributeMaxDynamicSharedMemorySize, SMEM1);

    float *R0, *R1;
    cudaGetSymbolAddress((void**)&R0, g_R0);
    cudaGetSymbolAddress((void**)&R1, g_R1);

    // layer 0
    prep0a_kernel<<<512, 256>>>(x, axon);
    gemm0s_kernel<<<dim3(32, SPLITK), GT, SMEMG>>>(W);
    scan_kernel<<<1024, 256>>>(thr, 0, R0);

    const float* rin = R0;
    for (int l = 1; l < 4; l++) {
        prep1g_kernel<<<128, 256>>>(rin, axon + l * Dc);
        gemm1s_kernel<<<dim3(32, SPLITK), GT, SMEM1>>>(
            W + (size_t)l * Nc * Dc);
        float* rout = (l & 1) ? R1 : R0;
        scan_kernel<<<1024, 256>>>(thr, l, rout);
        rin = rout;
    }
    out_kernel<<<512, 256>>>(rin, out_idx, (float*)d_out);
}

// round 15
// speedup vs baseline: 1.0319x; 1.0319x over previous
#include <cuda_runtime.h>
#include <cuda_bf16.h>
#include <cstdint>

// ---------------------------------------------------------------------------
// StableSpikingCoreFlow, round 15 = round 14 (112.7us, rel_err 0.0) with the
// R/scan stage deleted: spike counts are computed AT THE GATHER SITE from the
// splitK planes (bit-identical tree-4 merge + exact scan), so the 4 scan
// kernels, both R buffers, and the separate out pass disappear (14 -> 9
// launches, ~20MB/layer less traffic). GEMMs identical to round 14.
// ---------------------------------------------------------------------------

#define Bc 128
#define Dc 2048
#define Nc 2048
#define Tc 64
#define OUTc 1024
#define SPLITK 4
#define GT  256

#define ROWB 144             // 64 bf16 (128B) + 16B pad
#define ATILE (128 * ROWB)   // 18432 B
#define BT64  (64 * ROWB)    //  9216 B
#define BUF1  (ATILE + 3 * BT64)
#define SMEM1 (2 * BUF1)     // 92160 B
#define BUFG  (3 * ATILE + 3 * BT64)   // 82944 B
#define SMEMG (2 * BUFG)               // 165888 B

#define APIECE (Bc * Dc)
#define PL (Bc * Nc)         // plane stride

__device__ __nv_bfloat16 g_A[3 * APIECE];
__device__ float g_P[SPLITK * PL];

// ---------------------------------------------------------------------------
__device__ __forceinline__ void cp16(uint32_t dst, const void* src) {
    asm volatile("cp.async.cg.shared.global [%0], [%1], 16;\n" :: "r"(dst), "l"(src));
}
#define CP_COMMIT() asm volatile("cp.async.commit_group;\n" ::: "memory")
#define CP_WAIT(n)  asm volatile("cp.async.wait_group %0;\n" :: "n"(n) : "memory")

__device__ __forceinline__ void mma16816(float* c, const uint32_t* a,
                                         uint32_t b0, uint32_t b1) {
    asm volatile(
        "mma.sync.aligned.m16n8k16.row.col.f32.bf16.bf16.f32 "
        "{%0,%1,%2,%3},{%4,%5,%6,%7},{%8,%9},{%0,%1,%2,%3};\n"
        : "+f"(c[0]), "+f"(c[1]), "+f"(c[2]), "+f"(c[3])
        : "r"(a[0]), "r"(a[1]), "r"(a[2]), "r"(a[3]), "r"(b0), "r"(b1));
}

__device__ __forceinline__ uint32_t lds32c(const char* p) {
    return *(const uint32_t*)p;
}

__device__ __forceinline__ float bfround(float v) {
    return __bfloat162float(__float2bfloat16_rn(v));
}
__device__ __forceinline__ unsigned bfu(float v) {
    return (unsigned)__bfloat16_as_ushort(__float2bfloat16_rn(v));
}
__device__ __forceinline__ uint32_t pk(unsigned lo, unsigned hi) {
    return lo | (hi << 16);
}
// v = p0+p1+p2 + O(2^-25 v); residual subtractions exact
__device__ __forceinline__ void split3(float v, unsigned& u0, unsigned& u1,
                                       unsigned& u2) {
    float r1 = v - bfround(v);
    float r2 = r1 - bfround(r1);
    u0 = bfu(v); u1 = bfu(r1); u2 = bfu(r2);
}

// exact fp32 semantics of the reference spike scan; returns COUNT (0..64)
__device__ __forceinline__ float spike_count(float a, float thr) {
    int c;
    if (a <= 0.f) c = 0;
    else if (a > thr) c = Tc;
    else {
        float m = 0.f; c = 0;
        for (int t = 0; t < Tc; t++) { m += a; if (m > thr) { m -= thr; c++; } }
    }
    return (float)c;
}

// fixed-order tree-4 merge of splitK planes at column idx, then exact /64
__device__ __forceinline__ float plane_avg(int idx) {
    float e0 = g_P[idx];
    float e1 = g_P[PL + idx];
    float e2 = g_P[2 * PL + idx];
    float e3 = g_P[3 * PL + idx];
    return __fadd_rn(__fadd_rn(e0, e1), __fadd_rn(e2, e3)) * 0.015625f;
}

#define KFOLD(acc, ks, kc) do {                                      \
        float y = __fsub_rn((acc), (kc));                            \
        float t = __fadd_rn((ks), y);                                \
        (kc) = __fsub_rn(__fsub_rn(t, (ks)), y);                     \
        (ks) = t;                                                    \
        (acc) = 0.f;                                                 \
    } while (0)

// ---------------------------------------------------------------------------
// layer-0 prep: gather + split 64*x into 3 bf16 piece matrices (2 k/thread)
__global__ void prep0a_kernel(const float* __restrict__ x,
                              const int* __restrict__ axon) {
    int idx = blockIdx.x * blockDim.x + threadIdx.x;
    if (idx >= Bc * Dc / 2) return;
    int b = idx >> 10, a = (idx & 1023) * 2;
    unsigned p0, p1, p2, q0, q1, q2;
    split3(64.0f * x[(b << 11) + axon[a]],     p0, p1, p2);
    split3(64.0f * x[(b << 11) + axon[a + 1]], q0, q1, q2);
    size_t off = (size_t)b * Dc + a;
    *(uint32_t*)(g_A + off)              = pk(p0, q0);
    *(uint32_t*)(g_A + APIECE + off)     = pk(p1, q1);
    *(uint32_t*)(g_A + 2 * APIECE + off) = pk(p2, q2);
}

// layers>=1 prep: spike counts computed AT THE GATHER SITE from the planes
// (bit-identical to scan+gather of rounds 10-14), written as exact bf16.
__global__ void prepA_kernel(const int* __restrict__ axon,
                             const float* __restrict__ thr, int lprev) {
    int idx = blockIdx.x * blockDim.x + threadIdx.x;
    if (idx >= Bc * Dc / 2) return;
    int b = idx >> 10, a = (idx & 1023) * 2;
    int i0 = axon[a], i1 = axon[a + 1];
    const float th = thr[lprev];
    float c0 = spike_count(plane_avg((b << 11) + i0), th);
    float c1 = spike_count(plane_avg((b << 11) + i1), th);
    *(uint32_t*)(g_A + (size_t)b * Dc + a) = pk(bfu(c0), bfu(c1));
}

// final output: spike counts at out_idx columns, straight from the planes
__global__ void outF_kernel(const int* __restrict__ out_idx,
                            const float* __restrict__ thr,
                            float* __restrict__ out) {
    int idx = blockIdx.x * blockDim.x + threadIdx.x;
    if (idx >= Bc * OUTc) return;
    int b = idx >> 10, o = idx & 1023;
    int n = out_idx[o];
    out[idx] = spike_count(plane_avg((b << 11) + n), thr[3]);
}

// ---------------------------------------------------------------------------
// layer-0 GEMM: 6 piece-pairs, W split in-kernel, splitK=4,
// Kahan fold every kk (16 k-cols; measured rel_err 0.0 in round 14).
__global__ __launch_bounds__(GT, 1)
void gemm0s_kernel(const float* __restrict__ W) {
    extern __shared__ char smch[];
    const int tid = threadIdx.x;
    const int w = tid >> 5, lane = tid & 31;
    const int wm = w & 3, wn = w >> 2;
    const int g = lane >> 2, tig = lane & 3;
    const int bn = blockIdx.x * 64;
    const size_t k0 = (size_t)blockIdx.y * (Dc / SPLITK);
    const uint32_t smb = (uint32_t)__cvta_generic_to_shared(smch);
    const int nPh = (Dc / SPLITK) / 64;   // 8

    const int ch = tid & 7;
    const int arow = tid >> 3;
    const uint32_t dAbase = smb + arow * ROWB + ch * 16;
    const size_t sAoff = (size_t)arow * Dc + k0 + ch * 8;

    const int vrow = tid >> 2;
    const int vq   = tid & 3;
    const float* wp = W + (size_t)(bn + vrow) * Dc + k0 + vq * 4;
    const uint32_t bsts = smb + 3 * ATILE + vrow * ROWB + vq * 8;

#define FA0(p, buf) do {                                                     \
        uint32_t bo = (uint32_t)(buf) * BUFG;                                \
        _Pragma("unroll")                                                    \
        for (int pc = 0; pc < 3; pc++)                                       \
            _Pragma("unroll")                                                \
            for (int r = 0; r < 4; r++)                                      \
                cp16(dAbase + bo + pc * ATILE + r * (32 * ROWB),             \
                     g_A + pc * APIECE + sAoff + (size_t)r * (32 * Dc)       \
                         + (size_t)(p) * 64);                                \
        CP_COMMIT();                                                         \
    } while (0)

#define WLOAD(wr, p) do {                                                    \
        _Pragma("unroll")                                                    \
        for (int jj = 0; jj < 4; jj++)                                       \
            wr[jj] = *(const float4*)(wp + (size_t)(p) * 64 + jj * 16);      \
    } while (0)

#define FB0(buf, wr) do {                                                    \
        uint32_t ba = bsts + (uint32_t)(buf) * BUFG;                         \
        _Pragma("unroll")                                                    \
        for (int jj = 0; jj < 4; jj++) {                                     \
            float e4[4] = {wr[jj].x, wr[jj].y, wr[jj].z, wr[jj].w};          \
            unsigned q0[4], q1[4], q2[4];                                    \
            _Pragma("unroll")                                                \
            for (int i = 0; i < 4; i++)                                      \
                split3(e4[i], q0[i], q1[i], q2[i]);                          \
            uint32_t col = ba + jj * 32;                                     \
            asm volatile("st.shared.v2.b32 [%0], {%1,%2};\n"                 \
                :: "r"(col), "r"(pk(q0[0], q0[1])), "r"(pk(q0[2], q0[3]))); \
            asm volatile("st.shared.v2.b32 [%0], {%1,%2};\n"                 \
                :: "r"(col + BT64), "r"(pk(q1[0], q1[1])), "r"(pk(q1[2], q1[3]))); \
            asm volatile("st.shared.v2.b32 [%0], {%1,%2};\n"                 \
                :: "r"(col + 2 * BT64), "r"(pk(q2[0], q2[1])), "r"(pk(q2[2], q2[3]))); \
        }                                                                    \
    } while (0)

    float acc[2][4][4], ks[2][4][4], kc[2][4][4];
#pragma unroll
    for (int mt = 0; mt < 2; mt++)
#pragma unroll
        for (int j = 0; j < 4; j++)
#pragma unroll
            for (int q = 0; q < 4; q++) {
                acc[mt][j][q] = 0.f; ks[mt][j][q] = 0.f; kc[mt][j][q] = 0.f;
            }

    float4 wr[4];
    WLOAD(wr, 0); FB0(0, wr); FA0(0, 0);
    WLOAD(wr, 1); FB0(1, wr); FA0(1, 1);
    WLOAD(wr, 2);

    for (int p = 0; p < nPh; p++) {
        if (p + 1 < nPh) { CP_WAIT(1); } else { CP_WAIT(0); }
        __syncthreads();
        const char* Ab = smch + (p & 1) * BUFG;
        const char* Bb = Ab + 3 * ATILE;
#pragma unroll
        for (int kk = 0; kk < 4; kk++) {
            uint32_t a[3][2][4];
#pragma unroll
            for (int pc = 0; pc < 3; pc++)
#pragma unroll
                for (int mt = 0; mt < 2; mt++) {
                    const char* ap = Ab + pc * ATILE
                                   + (wm * 32 + mt * 16 + g) * ROWB
                                   + kk * 32 + tig * 4;
                    a[pc][mt][0] = lds32c(ap);
                    a[pc][mt][1] = lds32c(ap + 8 * ROWB);
                    a[pc][mt][2] = lds32c(ap + 16);
                    a[pc][mt][3] = lds32c(ap + 8 * ROWB + 16);
                }
#pragma unroll
            for (int j = 0; j < 4; j++) {
                const char* brow = Bb + (wn * 32 + j * 8 + g) * ROWB
                                 + kk * 32 + tig * 4;
                uint32_t b00 = lds32c(brow);
                uint32_t b01 = lds32c(brow + 16);
                uint32_t b10 = lds32c(brow + BT64);
                uint32_t b11 = lds32c(brow + BT64 + 16);
                uint32_t b20 = lds32c(brow + 2 * BT64);
                uint32_t b21 = lds32c(brow + 2 * BT64 + 16);
#pragma unroll
                for (int mt = 0; mt < 2; mt++) {
                    mma16816(acc[mt][j], a[0][mt], b00, b01);  // a0*w0
                    mma16816(acc[mt][j], a[0][mt], b10, b11);  // a0*w1
                    mma16816(acc[mt][j], a[0][mt], b20, b21);  // a0*w2
                    mma16816(acc[mt][j], a[1][mt], b00, b01);  // a1*w0
                    mma16816(acc[mt][j], a[1][mt], b10, b11);  // a1*w1
                    mma16816(acc[mt][j], a[2][mt], b00, b01);  // a2*w0
                }
            }
            // Kahan fold every kk: chunk = 16 full-magnitude k + corrections
#pragma unroll
            for (int mt = 0; mt < 2; mt++)
#pragma unroll
                for (int j = 0; j < 4; j++)
#pragma unroll
                    for (int q = 0; q < 4; q++)
                        KFOLD(acc[mt][j][q], ks[mt][j][q], kc[mt][j][q]);
        }
        __syncthreads();
        if (p + 2 < nPh) {
            FB0(p & 1, wr);
            FA0(p + 2, p & 1);
            if (p + 3 < nPh) WLOAD(wr, p + 3);
        }
    }
#undef FA0
#undef FB0
#undef WLOAD

    float* plane = g_P + (size_t)blockIdx.y * PL;
#pragma unroll
    for (int mt = 0; mt < 2; mt++)
#pragma unroll
        for (int j = 0; j < 4; j++) {
            int m = wm * 32 + mt * 16 + g;
            int n = bn + wn * 32 + j * 8 + 2 * tig;
            float r0 = __fsub_rn(ks[mt][j][0], kc[mt][j][0]);
            float r1 = __fsub_rn(ks[mt][j][1], kc[mt][j][1]);
            float r2 = __fsub_rn(ks[mt][j][2], kc[mt][j][2]);
            float r3 = __fsub_rn(ks[mt][j][3], kc[mt][j][3]);
            *(float2*)&plane[(size_t)m * Nc + n]       = make_float2(r0, r1);
            *(float2*)&plane[(size_t)(m + 8) * Nc + n] = make_float2(r2, r3);
        }
}

// ---------------------------------------------------------------------------
// layers>=1 GEMM: identical to rounds 12/13/14 (measured rel_err 0.0)
__global__ __launch_bounds__(GT, 1)
void gemm1s_kernel(const float* __restrict__ W) {
    extern __shared__ char smch[];
    const int tid = threadIdx.x;
    const int w = tid >> 5, lane = tid & 31;
    const int wm = w & 3, wn = w >> 2;
    const int g = lane >> 2, tig = lane & 3;
    const int bn = blockIdx.x * 64;
    const size_t k0 = (size_t)blockIdx.y * (Dc / SPLITK);
    const uint32_t smb = (uint32_t)__cvta_generic_to_shared(smch);
    const int nPh = (Dc / SPLITK) / 64;   // 8

    const int ch = tid & 7;
    const __nv_bfloat16* sA[4];
    uint32_t dA[4];
#pragma unroll
    for (int r = 0; r < 4; r++) {
        int row = (tid + r * GT) >> 3;
        sA[r] = g_A + (size_t)row * Dc + k0 + ch * 8;
        dA[r] = smb + row * ROWB + ch * 16;
    }

    const int vrow = tid >> 2;
    const int vq   = tid & 3;
    const float* wp = W + (size_t)(bn + vrow) * Dc + k0 + vq * 4;
    const uint32_t bsts = smb + ATILE + vrow * ROWB + vq * 8;

#define FA(p, buf) do {                                             \
        uint32_t bo = (uint32_t)(buf) * BUF1;                       \
        _Pragma("unroll")                                           \
        for (int r = 0; r < 4; r++)                                 \
            cp16(dA[r] + bo, sA[r] + (size_t)(p) * 64);             \
        CP_COMMIT();                                                \
    } while (0)

#define WLOAD(wr, p) do {                                           \
        _Pragma("unroll")                                           \
        for (int jj = 0; jj < 4; jj++)                              \
            wr[jj] = *(const float4*)(wp + (size_t)(p) * 64 + jj * 16); \
    } while (0)

#define FB(buf, wr) do {                                            \
        uint32_t ba = bsts + (uint32_t)(buf) * BUF1;                \
        _Pragma("unroll")                                           \
        for (int jj = 0; jj < 4; jj++) {                            \
            float e4[4] = {wr[jj].x, wr[jj].y, wr[jj].z, wr[jj].w}; \
            unsigned q0[4], q1[4], q2[4];                           \
            _Pragma("unroll")                                       \
            for (int i = 0; i < 4; i++)                             \
                split3(e4[i], q0[i], q1[i], q2[i]);                 \
            uint32_t col = ba + jj * 32;                            \
            asm volatile("st.shared.v2.b32 [%0], {%1,%2};\n"        \
                :: "r"(col), "r"(pk(q0[0], q0[1])), "r"(pk(q0[2], q0[3]))); \
            asm volatile("st.shared.v2.b32 [%0], {%1,%2};\n"        \
                :: "r"(col + 64 * ROWB), "r"(pk(q1[0], q1[1])), "r"(pk(q1[2], q1[3]))); \
            asm volatile("st.shared.v2.b32 [%0], {%1,%2};\n"        \
                :: "r"(col + 128 * ROWB), "r"(pk(q2[0], q2[1])), "r"(pk(q2[2], q2[3]))); \
        }                                                           \
    } while (0)

    float acc[2][4][4], ks[2][4][4], kc[2][4][4];
#pragma unroll
    for (int mt = 0; mt < 2; mt++)
#pragma unroll
        for (int j = 0; j < 4; j++)
#pragma unroll
            for (int q = 0; q < 4; q++) {
                acc[mt][j][q] = 0.f; ks[mt][j][q] = 0.f; kc[mt][j][q] = 0.f;
            }

    float4 wr[4];
    WLOAD(wr, 0); FB(0, wr); FA(0, 0);
    WLOAD(wr, 1); FB(1, wr); FA(1, 1);
    WLOAD(wr, 2);

    for (int p = 0; p < nPh; p++) {
        if (p + 1 < nPh) { CP_WAIT(1); } else { CP_WAIT(0); }
        __syncthreads();
        const char* Ab = smch + (p & 1) * BUF1;
        const char* Bb = Ab + ATILE;
#pragma unroll
        for (int kk = 0; kk < 4; kk++) {
            uint32_t a[2][4];
#pragma unroll
            for (int mt = 0; mt < 2; mt++) {
                const char* ap = Ab + (wm * 32 + mt * 16 + g) * ROWB
                               + kk * 32 + tig * 4;
                a[mt][0] = lds32c(ap);
                a[mt][1] = lds32c(ap + 8 * ROWB);
                a[mt][2] = lds32c(ap + 16);
                a[mt][3] = lds32c(ap + 8 * ROWB + 16);
            }
#pragma unroll
            for (int pc = 0; pc < 3; pc++) {
#pragma unroll
                for (int j = 0; j < 4; j++) {
                    const char* bp = Bb + pc * (64 * ROWB)
                                   + (wn * 32 + j * 8 + g) * ROWB
                                   + kk * 32 + tig * 4;
                    uint32_t b0 = lds32c(bp);
                    uint32_t b1 = lds32c(bp + 16);
                    mma16816(acc[0][j], a[0], b0, b1);
                    mma16816(acc[1][j], a[1], b0, b1);
                }
            }
        }
        __syncthreads();
        if (p + 2 < nPh) {
            FB(p & 1, wr);
            FA(p + 2, p & 1);
            if (p + 3 < nPh) WLOAD(wr, p + 3);
        }

#pragma unroll
        for (int mt = 0; mt < 2; mt++)
#pragma unroll
            for (int j = 0; j < 4; j++)
#pragma unroll
                for (int q = 0; q < 4; q++)
                    KFOLD(acc[mt][j][q], ks[mt][j][q], kc[mt][j][q]);
    }
#undef FA
#undef FB
#undef WLOAD

    float* plane = g_P + (size_t)blockIdx.y * PL;
#pragma unroll
    for (int mt = 0; mt < 2; mt++)
#pragma unroll
        for (int j = 0; j < 4; j++) {
            int m = wm * 32 + mt * 16 + g;
            int n = bn + wn * 32 + j * 8 + 2 * tig;
            float r0 = __fsub_rn(ks[mt][j][0], kc[mt][j][0]);
            float r1 = __fsub_rn(ks[mt][j][1], kc[mt][j][1]);
            float r2 = __fsub_rn(ks[mt][j][2], kc[mt][j][2]);
            float r3 = __fsub_rn(ks[mt][j][3], kc[mt][j][3]);
            *(float2*)&plane[(size_t)m * Nc + n]       = make_float2(r0, r1);
            *(float2*)&plane[(size_t)(m + 8) * Nc + n] = make_float2(r2, r3);
        }
}

// ---------------------------------------------------------------------------
extern "C" void kernel_launch(void* const* d_in, const int* in_sizes, int n_in,
                              void* d_out, int out_size)
{
    const float* x       = (const float*)d_in[0];
    const float* W       = (const float*)d_in[1];
    const float* thr     = (const float*)d_in[2];
    const int*   axon    = (const int*)  d_in[3];
    const int*   out_idx = (const int*)  d_in[4];
    (void)in_sizes; (void)n_in; (void)out_size;

    cudaFuncSetAttribute(gemm0s_kernel,
                         cudaFuncAttributeMaxDynamicSharedMemorySize, SMEMG);
    cudaFuncSetAttribute(gemm1s_kernel,
                         cudaFuncAttributeMaxDynamicSharedMemorySize, SMEM1);

    // layer 0
    prep0a_kernel<<<512, 256>>>(x, axon);
    gemm0s_kernel<<<dim3(32, SPLITK), GT, SMEMG>>>(W);

    // layers 1..3: gather+spike-count fused (reads planes), then GEMM
    for (int l = 1; l < 4; l++) {
        prepA_kernel<<<512, 256>>>(axon + l * Dc, thr, l - 1);
        gemm1s_kernel<<<dim3(32, SPLITK), GT, SMEM1>>>(
            W + (size_t)l * Nc * Dc);
    }

    // final output: spike counts at out_idx straight from the planes
    outF_kernel<<<512, 256>>>(out_idx, thr, (float*)d_out);
}

// round 16
// speedup vs baseline: 1.0380x; 1.0059x over previous
#include <cuda_runtime.h>
#include <cuda_bf16.h>
#include <cstdint>

// ---------------------------------------------------------------------------
// StableSpikingCoreFlow, round 16 = round 15 (109.2us, rel_err 0.0) with both
// GEMMs rebuilt at 512 threads / 16 warps (warp tile 32m x 16n): per-warp MMA
// count halves, warps/SMSP doubles (latency hiding), regs fit the 128 cap.
// Per-output-element accumulation order is BIT-IDENTICAL to round 15 (same
// k-order, product set, fold cadence) -> rel_err 0.0 preserved.
// ---------------------------------------------------------------------------

#define Bc 128
#define Dc 2048
#define Nc 2048
#define Tc 64
#define OUTc 1024
#define SPLITK 4
#define GT  512

#define ROWB 144             // 64 bf16 (128B) + 16B pad
#define ATILE (128 * ROWB)   // 18432 B
#define BT64  (64 * ROWB)    //  9216 B
#define BUF1  (ATILE + 3 * BT64)
#define SMEM1 (2 * BUF1)     // 92160 B
#define BUFG  (3 * ATILE + 3 * BT64)   // 82944 B
#define SMEMG (2 * BUFG)               // 165888 B

#define APIECE (Bc * Dc)
#define PL (Bc * Nc)

__device__ __nv_bfloat16 g_A[3 * APIECE];
__device__ float g_P[SPLITK * PL];

// ---------------------------------------------------------------------------
__device__ __forceinline__ void cp16(uint32_t dst, const void* src) {
    asm volatile("cp.async.cg.shared.global [%0], [%1], 16;\n" :: "r"(dst), "l"(src));
}
#define CP_COMMIT() asm volatile("cp.async.commit_group;\n" ::: "memory")
#define CP_WAIT(n)  asm volatile("cp.async.wait_group %0;\n" :: "n"(n) : "memory")

__device__ __forceinline__ void mma16816(float* c, const uint32_t* a,
                                         uint32_t b0, uint32_t b1) {
    asm volatile(
        "mma.sync.aligned.m16n8k16.row.col.f32.bf16.bf16.f32 "
        "{%0,%1,%2,%3},{%4,%5,%6,%7},{%8,%9},{%0,%1,%2,%3};\n"
        : "+f"(c[0]), "+f"(c[1]), "+f"(c[2]), "+f"(c[3])
        : "r"(a[0]), "r"(a[1]), "r"(a[2]), "r"(a[3]), "r"(b0), "r"(b1));
}

__device__ __forceinline__ uint32_t lds32c(const char* p) {
    return *(const uint32_t*)p;
}

__device__ __forceinline__ float bfround(float v) {
    return __bfloat162float(__float2bfloat16_rn(v));
}
__device__ __forceinline__ unsigned bfu(float v) {
    return (unsigned)__bfloat16_as_ushort(__float2bfloat16_rn(v));
}
__device__ __forceinline__ uint32_t pk(unsigned lo, unsigned hi) {
    return lo | (hi << 16);
}
// v = p0+p1+p2 + O(2^-25 v); residual subtractions exact
__device__ __forceinline__ void split3(float v, unsigned& u0, unsigned& u1,
                                       unsigned& u2) {
    float r1 = v - bfround(v);
    float r2 = r1 - bfround(r1);
    u0 = bfu(v); u1 = bfu(r1); u2 = bfu(r2);
}

// exact fp32 semantics of the reference spike scan; returns COUNT (0..64)
__device__ __forceinline__ float spike_count(float a, float thr) {
    int c;
    if (a <= 0.f) c = 0;
    else if (a > thr) c = Tc;
    else {
        float m = 0.f; c = 0;
        for (int t = 0; t < Tc; t++) { m += a; if (m > thr) { m -= thr; c++; } }
    }
    return (float)c;
}

// fixed-order tree-4 merge of splitK planes at column idx, then exact /64
__device__ __forceinline__ float plane_avg(int idx) {
    float e0 = g_P[idx];
    float e1 = g_P[PL + idx];
    float e2 = g_P[2 * PL + idx];
    float e3 = g_P[3 * PL + idx];
    return __fadd_rn(__fadd_rn(e0, e1), __fadd_rn(e2, e3)) * 0.015625f;
}

#define KFOLD(acc, ks, kc) do {                                      \
        float y = __fsub_rn((acc), (kc));                            \
        float t = __fadd_rn((ks), y);                                \
        (kc) = __fsub_rn(__fsub_rn(t, (ks)), y);                     \
        (ks) = t;                                                    \
        (acc) = 0.f;                                                 \
    } while (0)

// W split of 8 floats -> 3 pieces, one st.v4.b32 per piece
#define WSPLIT8_STS(base, e8) do {                                   \
        unsigned q0[8], q1[8], q2[8];                                \
        _Pragma("unroll")                                            \
        for (int i = 0; i < 8; i++) split3((e8)[i], q0[i], q1[i], q2[i]); \
        asm volatile("st.shared.v4.b32 [%0], {%1,%2,%3,%4};\n"       \
            :: "r"(base), "r"(pk(q0[0], q0[1])), "r"(pk(q0[2], q0[3])), \
               "r"(pk(q0[4], q0[5])), "r"(pk(q0[6], q0[7])));        \
        asm volatile("st.shared.v4.b32 [%0], {%1,%2,%3,%4};\n"       \
            :: "r"((base) + BT64), "r"(pk(q1[0], q1[1])), "r"(pk(q1[2], q1[3])), \
               "r"(pk(q1[4], q1[5])), "r"(pk(q1[6], q1[7])));        \
        asm volatile("st.shared.v4.b32 [%0], {%1,%2,%3,%4};\n"       \
            :: "r"((base) + 2 * BT64), "r"(pk(q2[0], q2[1])), "r"(pk(q2[2], q2[3])), \
               "r"(pk(q2[4], q2[5])), "r"(pk(q2[6], q2[7])));        \
    } while (0)

// ---------------------------------------------------------------------------
// layer-0 prep: gather + split 64*x into 3 bf16 piece matrices
__global__ void prep0a_kernel(const float* __restrict__ x,
                              const int* __restrict__ axon) {
    int idx = blockIdx.x * blockDim.x + threadIdx.x;
    if (idx >= Bc * Dc / 2) return;
    int b = idx >> 10, a = (idx & 1023) * 2;
    unsigned p0, p1, p2, q0, q1, q2;
    split3(64.0f * x[(b << 11) + axon[a]],     p0, p1, p2);
    split3(64.0f * x[(b << 11) + axon[a + 1]], q0, q1, q2);
    size_t off = (size_t)b * Dc + a;
    *(uint32_t*)(g_A + off)              = pk(p0, q0);
    *(uint32_t*)(g_A + APIECE + off)     = pk(p1, q1);
    *(uint32_t*)(g_A + 2 * APIECE + off) = pk(p2, q2);
}

// layers>=1 prep: spike counts computed at the gather site from the planes
__global__ void prepA_kernel(const int* __restrict__ axon,
                             const float* __restrict__ thr, int lprev) {
    int idx = blockIdx.x * blockDim.x + threadIdx.x;
    if (idx >= Bc * Dc / 2) return;
    int b = idx >> 10, a = (idx & 1023) * 2;
    int i0 = axon[a], i1 = axon[a + 1];
    const float th = thr[lprev];
    float c0 = spike_count(plane_avg((b << 11) + i0), th);
    float c1 = spike_count(plane_avg((b << 11) + i1), th);
    *(uint32_t*)(g_A + (size_t)b * Dc + a) = pk(bfu(c0), bfu(c1));
}

// final output: spike counts at out_idx columns from the planes
__global__ void outF_kernel(const int* __restrict__ out_idx,
                            const float* __restrict__ thr,
                            float* __restrict__ out) {
    int idx = blockIdx.x * blockDim.x + threadIdx.x;
    if (idx >= Bc * OUTc) return;
    int b = idx >> 10, o = idx & 1023;
    int n = out_idx[o];
    out[idx] = spike_count(plane_avg((b << 11) + n), thr[3]);
}

// ---------------------------------------------------------------------------
// layer-0 GEMM: 512 threads, 16 warps (4m x 4n), warp tile 32m x 16n.
// 6 piece-pairs, W split in-kernel, splitK=4, Kahan fold per kk (16 k).
__global__ __launch_bounds__(GT, 1)
void gemm0s_kernel(const float* __restrict__ W) {
    extern __shared__ char smch[];
    const int tid = threadIdx.x;
    const int w = tid >> 5, lane = tid & 31;
    const int wm = w & 3, wn = w >> 2;           // 4 x 4 warp grid
    const int g = lane >> 2, tig = lane & 3;
    const int bn = blockIdx.x * 64;
    const size_t k0 = (size_t)blockIdx.y * (Dc / SPLITK);
    const uint32_t smb = (uint32_t)__cvta_generic_to_shared(smch);
    const int nPh = (Dc / SPLITK) / 64;   // 8

    // A cp.async: 3 pieces x 1024 chunks, 6 per thread
    const int ch = tid & 7;
    const int arow0 = tid >> 3;          // 0..63
    // W loader: 64 rows x 64 cols fp32/phase; thread: row tid>>3, 8 cols
    const int vrow = tid >> 3;
    const int vq   = tid & 7;
    const float* wp = W + (size_t)(bn + vrow) * Dc + k0 + vq * 8;
    const uint32_t bsts = smb + 3 * ATILE + vrow * ROWB + vq * 16;

#define FA0(p, buf) do {                                                     \
        uint32_t bo = (uint32_t)(buf) * BUFG;                                \
        _Pragma("unroll")                                                    \
        for (int pc = 0; pc < 3; pc++)                                       \
            _Pragma("unroll")                                                \
            for (int r = 0; r < 2; r++)                                      \
                cp16(smb + bo + pc * ATILE + (arow0 + r * 64) * ROWB + ch * 16, \
                     g_A + pc * APIECE + (size_t)(arow0 + r * 64) * Dc + k0  \
                         + ch * 8 + (size_t)(p) * 64);                       \
        CP_COMMIT();                                                         \
    } while (0)

#define WLOAD(wr, p) do {                                                    \
        wr[0] = *(const float4*)(wp + (size_t)(p) * 64);                     \
        wr[1] = *(const float4*)(wp + (size_t)(p) * 64 + 4);                 \
    } while (0)

#define FB0(buf, wr) do {                                                    \
        float e8[8] = {wr[0].x, wr[0].y, wr[0].z, wr[0].w,                   \
                       wr[1].x, wr[1].y, wr[1].z, wr[1].w};                  \
        WSPLIT8_STS(bsts + (uint32_t)(buf) * BUFG, e8);                      \
    } while (0)

    float acc[2][2][4], ks[2][2][4], kc[2][2][4];
#pragma unroll
    for (int mt = 0; mt < 2; mt++)
#pragma unroll
        for (int j = 0; j < 2; j++)
#pragma unroll
            for (int q = 0; q < 4; q++) {
                acc[mt][j][q] = 0.f; ks[mt][j][q] = 0.f; kc[mt][j][q] = 0.f;
            }

    float4 wr[2];
    WLOAD(wr, 0); FB0(0, wr); FA0(0, 0);
    WLOAD(wr, 1); FB0(1, wr); FA0(1, 1);
    WLOAD(wr, 2);

    for (int p = 0; p < nPh; p++) {
        if (p + 1 < nPh) { CP_WAIT(1); } else { CP_WAIT(0); }
        __syncthreads();
        const char* Ab = smch + (p & 1) * BUFG;
        const char* Bb = Ab + 3 * ATILE;
#pragma unroll
        for (int kk = 0; kk < 4; kk++) {
#pragma unroll
            for (int mt = 0; mt < 2; mt++) {
                uint32_t a[3][4];
#pragma unroll
                for (int pc = 0; pc < 3; pc++) {
                    const char* ap = Ab + pc * ATILE
                                   + (wm * 32 + mt * 16 + g) * ROWB
                                   + kk * 32 + tig * 4;
                    a[pc][0] = lds32c(ap);
                    a[pc][1] = lds32c(ap + 8 * ROWB);
                    a[pc][2] = lds32c(ap + 16);
                    a[pc][3] = lds32c(ap + 8 * ROWB + 16);
                }
#pragma unroll
                for (int j = 0; j < 2; j++) {
                    const char* brow = Bb + (wn * 16 + j * 8 + g) * ROWB
                                     + kk * 32 + tig * 4;
                    uint32_t b00 = lds32c(brow);
                    uint32_t b01 = lds32c(brow + 16);
                    uint32_t b10 = lds32c(brow + BT64);
                    uint32_t b11 = lds32c(brow + BT64 + 16);
                    uint32_t b20 = lds32c(brow + 2 * BT64);
                    uint32_t b21 = lds32c(brow + 2 * BT64 + 16);
                    mma16816(acc[mt][j], a[0], b00, b01);  // a0*w0
                    mma16816(acc[mt][j], a[0], b10, b11);  // a0*w1
                    mma16816(acc[mt][j], a[0], b20, b21);  // a0*w2
                    mma16816(acc[mt][j], a[1], b00, b01);  // a1*w0
                    mma16816(acc[mt][j], a[1], b10, b11);  // a1*w1
                    mma16816(acc[mt][j], a[2], b00, b01);  // a2*w0
                }
            }
            // Kahan fold every kk (16 full-magnitude k; round-14 cadence)
#pragma unroll
            for (int mt = 0; mt < 2; mt++)
#pragma unroll
                for (int j = 0; j < 2; j++)
#pragma unroll
                    for (int q = 0; q < 4; q++)
                        KFOLD(acc[mt][j][q], ks[mt][j][q], kc[mt][j][q]);
        }
        __syncthreads();
        if (p + 2 < nPh) {
            FB0(p & 1, wr);
            FA0(p + 2, p & 1);
            if (p + 3 < nPh) WLOAD(wr, p + 3);
        }
    }
#undef FA0
#undef FB0
#undef WLOAD

    float* plane = g_P + (size_t)blockIdx.y * PL;
#pragma unroll
    for (int mt = 0; mt < 2; mt++)
#pragma unroll
        for (int j = 0; j < 2; j++) {
            int m = wm * 32 + mt * 16 + g;
            int n = bn + wn * 16 + j * 8 + 2 * tig;
            float r0 = __fsub_rn(ks[mt][j][0], kc[mt][j][0]);
            float r1 = __fsub_rn(ks[mt][j][1], kc[mt][j][1]);
            float r2 = __fsub_rn(ks[mt][j][2], kc[mt][j][2]);
            float r3 = __fsub_rn(ks[mt][j][3], kc[mt][j][3]);
            *(float2*)&plane[(size_t)m * Nc + n]       = make_float2(r0, r1);
            *(float2*)&plane[(size_t)(m + 8) * Nc + n] = make_float2(r2, r3);
        }
}

// ---------------------------------------------------------------------------
// layers>=1 GEMM: 512 threads, 16 warps, warp tile 32m x 16n; A counts,
// W split in-kernel; Kahan fold per 64-col phase (round-12/14/15 cadence).
__global__ __launch_bounds__(GT, 1)
void gemm1s_kernel(const float* __restrict__ W) {
    extern __shared__ char smch[];
    const int tid = threadIdx.x;
    const int w = tid >> 5, lane = tid & 31;
    const int wm = w & 3, wn = w >> 2;
    const int g = lane >> 2, tig = lane & 3;
    const int bn = blockIdx.x * 64;
    const size_t k0 = (size_t)blockIdx.y * (Dc / SPLITK);
    const uint32_t smb = (uint32_t)__cvta_generic_to_shared(smch);
    const int nPh = (Dc / SPLITK) / 64;   // 8

    const int ch = tid & 7;
    const int arow0 = tid >> 3;
    const int vrow = tid >> 3;
    const int vq   = tid & 7;
    const float* wp = W + (size_t)(bn + vrow) * Dc + k0 + vq * 8;
    const uint32_t bsts = smb + ATILE + vrow * ROWB + vq * 16;

#define FA(p, buf) do {                                                      \
        uint32_t bo = (uint32_t)(buf) * BUF1;                                \
        _Pragma("unroll")                                                    \
        for (int r = 0; r < 2; r++)                                          \
            cp16(smb + bo + (arow0 + r * 64) * ROWB + ch * 16,               \
                 g_A + (size_t)(arow0 + r * 64) * Dc + k0 + ch * 8           \
                     + (size_t)(p) * 64);                                    \
        CP_COMMIT();                                                         \
    } while (0)

#define WLOAD(wr, p) do {                                                    \
        wr[0] = *(const float4*)(wp + (size_t)(p) * 64);                     \
        wr[1] = *(const float4*)(wp + (size_t)(p) * 64 + 4);                 \
    } while (0)

#define FB(buf, wr) do {                                                     \
        float e8[8] = {wr[0].x, wr[0].y, wr[0].z, wr[0].w,                   \
                       wr[1].x, wr[1].y, wr[1].z, wr[1].w};                  \
        WSPLIT8_STS(bsts + (uint32_t)(buf) * BUF1, e8);                      \
    } while (0)

    float acc[2][2][4], ks[2][2][4], kc[2][2][4];
#pragma unroll
    for (int mt = 0; mt < 2; mt++)
#pragma unroll
        for (int j = 0; j < 2; j++)
#pragma unroll
            for (int q = 0; q < 4; q++) {
                acc[mt][j][q] = 0.f; ks[mt][j][q] = 0.f; kc[mt][j][q] = 0.f;
            }

    float4 wr[2];
    WLOAD(wr, 0); FB(0, wr); FA(0, 0);
    WLOAD(wr, 1); FB(1, wr); FA(1, 1);
    WLOAD(wr, 2);

    for (int p = 0; p < nPh; p++) {
        if (p + 1 < nPh) { CP_WAIT(1); } else { CP_WAIT(0); }
        __syncthreads();
        const char* Ab = smch + (p & 1) * BUF1;
        const char* Bb = Ab + ATILE;
#pragma unroll
        for (int kk = 0; kk < 4; kk++) {
#pragma unroll
            for (int mt = 0; mt < 2; mt++) {
                uint32_t a[4];
                const char* ap = Ab + (wm * 32 + mt * 16 + g) * ROWB
                               + kk * 32 + tig * 4;
                a[0] = lds32c(ap);
                a[1] = lds32c(ap + 8 * ROWB);
                a[2] = lds32c(ap + 16);
                a[3] = lds32c(ap + 8 * ROWB + 16);
#pragma unroll
                for (int pc = 0; pc < 3; pc++) {
#pragma unroll
                    for (int j = 0; j < 2; j++) {
                        const char* bp = Bb + pc * BT64
                                       + (wn * 16 + j * 8 + g) * ROWB
                                       + kk * 32 + tig * 4;
                        uint32_t b0 = lds32c(bp);
                        uint32_t b1 = lds32c(bp + 16);
                        mma16816(acc[mt][j], a, b0, b1);
                    }
                }
            }
        }
        __syncthreads();
        if (p + 2 < nPh) {
            FB(p & 1, wr);
            FA(p + 2, p & 1);
            if (p + 3 < nPh) WLOAD(wr, p + 3);
        }

        // Kahan fold per phase (64 main products + corrections)
#pragma unroll
        for (int mt = 0; mt < 2; mt++)
#pragma unroll
            for (int j = 0; j < 2; j++)
#pragma unroll
                for (int q = 0; q < 4; q++)
                    KFOLD(acc[mt][j][q], ks[mt][j][q], kc[mt][j][q]);
    }
#undef FA
#undef FB
#undef WLOAD

    float* plane = g_P + (size_t)blockIdx.y * PL;
#pragma unroll
    for (int mt = 0; mt < 2; mt++)
#pragma unroll
        for (int j = 0; j < 2; j++) {
            int m = wm * 32 + mt * 16 + g;
            int n = bn + wn * 16 + j * 8 + 2 * tig;
            float r0 = __fsub_rn(ks[mt][j][0], kc[mt][j][0]);
            float r1 = __fsub_rn(ks[mt][j][1], kc[mt][j][1]);
            float r2 = __fsub_rn(ks[mt][j][2], kc[mt][j][2]);
            float r3 = __fsub_rn(ks[mt][j][3], kc[mt][j][3]);
            *(float2*)&plane[(size_t)m * Nc + n]       = make_float2(r0, r1);
            *(float2*)&plane[(size_t)(m + 8) * Nc + n] = make_float2(r2, r3);
        }
}

// ---------------------------------------------------------------------------
extern "C" void kernel_launch(void* const* d_in, const int* in_sizes, int n_in,
                              void* d_out, int out_size)
{
    const float* x       = (const float*)d_in[0];
    const float* W       = (const float*)d_in[1];
    const float* thr     = (const float*)d_in[2];
    const int*   axon    = (const int*)  d_in[3];
    const int*   out_idx = (const int*)  d_in[4];
    (void)in_sizes; (void)n_in; (void)out_size;

    cudaFuncSetAttribute(gemm0s_kernel,
                         cudaFuncAttributeMaxDynamicSharedMemorySize, SMEMG);
    cudaFuncSetAttribute(gemm1s_kernel,
                         cudaFuncAttributeMaxDynamicSharedMemorySize, SMEM1);

    // layer 0
    prep0a_kernel<<<512, 256>>>(x, axon);
    gemm0s_kernel<<<dim3(32, SPLITK), GT, SMEMG>>>(W);

    // layers 1..3: gather+spike-count fused (reads planes), then GEMM
    for (int l = 1; l < 4; l++) {
        prepA_kernel<<<512, 256>>>(axon + l * Dc, thr, l - 1);
        gemm1s_kernel<<<dim3(32, SPLITK), GT, SMEM1>>>(
            W + (size_t)l * Nc * Dc);
    }

    // final output: spike counts at out_idx straight from the planes
    outF_kernel<<<512, 256>>>(out_idx, thr, (float*)d_out);
}